// round 10
// baseline (speedup 1.0000x reference)
#include <cuda_runtime.h>
#include <cuda_bf16.h>
#include <math.h>
#include <string.h>

typedef unsigned int u32;
typedef unsigned long long u64;

// ---------------------------------------------------------------------------
// Problem constants
// ---------------------------------------------------------------------------
constexpr int T    = 64;
constexpr int B    = 2048;
constexpr int H    = 256;
constexpr int H1   = 64;
constexpr int H2   = 64;
constexpr int OUTD = 601;
constexpr int RROWS = 64;
constexpr int NTILE = T * B / RROWS;   // 2048 MLP tiles

// ---------------------------------------------------------------------------
// PTX helpers
// ---------------------------------------------------------------------------
__device__ __forceinline__ u32 smem_u32(const void* p) {
    u32 a;
    asm("{ .reg .u64 t; cvta.to.shared.u64 t, %1; cvt.u32.u64 %0, t; }"
        : "=r"(a) : "l"(p));
    return a;
}
__device__ __forceinline__ void ldsm_x4(u32& r0, u32& r1, u32& r2, u32& r3, u32 addr) {
    asm volatile("ldmatrix.sync.aligned.m8n8.x4.shared.b16 {%0,%1,%2,%3}, [%4];"
                 : "=r"(r0), "=r"(r1), "=r"(r2), "=r"(r3) : "r"(addr));
}
__device__ __forceinline__ void mma_bf16(float* d, const u32* a, const u32* b) {
    asm volatile(
        "mma.sync.aligned.m16n8k16.row.col.f32.bf16.bf16.f32 "
        "{%0,%1,%2,%3}, {%4,%5,%6,%7}, {%8,%9}, {%0,%1,%2,%3};"
        : "+f"(d[0]), "+f"(d[1]), "+f"(d[2]), "+f"(d[3])
        : "r"(a[0]), "r"(a[1]), "r"(a[2]), "r"(a[3]), "r"(b[0]), "r"(b[1]));
}
__device__ __forceinline__ void cp16(u32 dst, const void* src) {
    asm volatile("cp.async.ca.shared.global [%0], [%1], 16;" :: "r"(dst), "l"(src));
}
__device__ __forceinline__ void cp_commit() {
    asm volatile("cp.async.commit_group;" ::: "memory");
}
template <int N>
__device__ __forceinline__ void cp_wait_group() {
    asm volatile("cp.async.wait_group %0;" :: "n"(N) : "memory");
}
__device__ __forceinline__ void cp_wait_all() {
    asm volatile("cp.async.wait_all;" ::: "memory");
}
__device__ __forceinline__ u32 bf2u(__nv_bfloat162 v) {
    u32 r; memcpy(&r, &v, 4); return r;
}
__device__ __forceinline__ float2 u2f2(u32 v) {
    __nv_bfloat162 b; memcpy(&b, &v, 4);
    return make_float2(__bfloat162float(b.x), __bfloat162float(b.y));
}
__device__ __forceinline__ u64 ffma2(u64 a, u64 b, u64 c) {
    u64 d; asm("fma.rn.f32x2 %0, %1, %2, %3;" : "=l"(d) : "l"(a), "l"(b), "l"(c));
    return d;
}
__device__ __forceinline__ u64 pack2(float x, float y) {
    u64 d; asm("mov.b64 %0, {%1, %2};" : "=l"(d) : "f"(x), "f"(y));
    return d;
}
__device__ __forceinline__ float2 unpack2(u64 v) {
    float2 r; asm("mov.b64 {%0, %1}, %2;" : "=f"(r.x), "=f"(r.y) : "l"(v));
    return r;
}
// cluster primitives
__device__ __forceinline__ u32 mapa_r(u32 addr, u32 rank) {
    u32 r; asm("mapa.shared::cluster.u32 %0, %1, %2;" : "=r"(r) : "r"(addr), "r"(rank));
    return r;
}
__device__ __forceinline__ void stc(u32 addr, u32 v) {
    asm volatile("st.shared::cluster.u32 [%0], %1;" :: "r"(addr), "r"(v) : "memory");
}
#define CLU_ARRIVE() asm volatile("barrier.cluster.arrive.aligned;" ::: "memory")
#define CLU_WAIT()   asm volatile("barrier.cluster.wait.aligned;" ::: "memory")

constexpr float LOG2E = 1.4426950408889634f;
__device__ __forceinline__ float fast_sigmoid(float v) {
    float e; asm("ex2.approx.f32 %0, %1;" : "=f"(e) : "f"(-LOG2E * v));
    float r; asm("rcp.approx.f32 %0, %1;" : "=f"(r) : "f"(1.f + e));
    return r;
}
__device__ __forceinline__ float fast_tanh(float v) {
    float e; asm("ex2.approx.f32 %0, %1;" : "=f"(e) : "f"(2.f * LOG2E * v));
    float r; asm("rcp.approx.f32 %0, %1;" : "=f"(r) : "f"(1.f + e));
    return 1.f - 2.f * r;
}
__device__ __forceinline__ float fast_elu(float v) {
    if (v > 0.f) return v;
    float e; asm("ex2.approx.f32 %0, %1;" : "=f"(e) : "f"(LOG2E * v));
    return e - 1.f;
}

// ---------------------------------------------------------------------------
// Device scratch
// ---------------------------------------------------------------------------
__device__ u32 g_hhi[(size_t)T * B * (H / 2)];   // [t][b][kp] bf16x2 hi (MLP input)
__device__ u32 g_hlo[(size_t)T * B * (H / 2)];   // [t][b][kp] bf16x2 lo
__device__ __nv_bfloat16 g_whi[(size_t)3 * H * H];
__device__ __nv_bfloat16 g_wlo[(size_t)3 * H * H];
__device__ u32 g_cnt[32 * 32];    // per-bg monotonic counters (128B apart)
__device__ u32 g_q;               // MLP tile queue

__global__ void prep_w_kernel(const float* __restrict__ w_hh)
{
    int i = blockIdx.x * blockDim.x + threadIdx.x;
    if (i < 3 * H * H) {
        float w = w_hh[i];
        __nv_bfloat16 hi = __float2bfloat16(w);
        g_whi[i] = hi;
        g_wlo[i] = __float2bfloat16(w - __bfloat162float(hi));
    }
    if (blockIdx.x == 0 && threadIdx.x < 32) {
        g_cnt[threadIdx.x * 32] = 0;
        if (threadIdx.x == 0) g_q = 0;
    }
}

// ---------------------------------------------------------------------------
// Fused persistent kernel: 132 blocks (33 clusters of 4) x 512 threads.
// Blocks 0..127 = 32 GRU clusters (cluster == the 4 jc-siblings of one bg);
// h exchanged via DSMEM pushes + cluster barriers. Blocks 128..131 = early
// MLP consumers; GRU blocks join the MLP queue after the recurrence.
// ---------------------------------------------------------------------------
constexpr int GRID_P = 132;   // cluster-4 residency cap on sm_103a
constexpr int NGRU   = 128;
constexpr int SM_WHI = 0;          // whi resident: [4 chunks][192 rows][128B] = 98304
constexpr int SM_WLO = 98304;      // wlo staging: 2 bufs x 24576 = 49152
constexpr int SM_A   = 147456;     // h bf16 hi/lo: [4 chunks][hi 8192 + lo 8192] = 65536
constexpr int SM_PRM = 212992;     // 7*64 f32 = 1792
constexpr int SM_Q   = 214784;     // queue broadcast slot
constexpr int FUSED_SMEM = 215040;

struct AccT { float a[3][2][4]; };

__device__ __forceinline__ void mma_section(AccT& A, u32 ab, u32 whb, u32 wlb,
                                            int wm, int wn,
                                            int a_row, int a_colh,
                                            int b_row, int b_colh)
{
    #pragma unroll
    for (int ks = 0; ks < 4; ks++) {
        u32 ahi[4], alo[4];
        {
            int r = wm * 16 + a_row;
            u32 off = (u32)(r * 128) + (u32)((ks * 32 + a_colh) ^ ((r & 7) << 4));
            ldsm_x4(ahi[0], ahi[1], ahi[2], ahi[3], ab + off);
            ldsm_x4(alo[0], alo[1], alo[2], alo[3], ab + 8192 + off);
        }
        #pragma unroll
        for (int g = 0; g < 3; g++) {
            int rr = g * 64 + wn * 16 + b_row;
            u32 off = (u32)(rr * 128) + (u32)((ks * 32 + b_colh) ^ ((rr & 7) << 4));
            u32 bh[4], bl[4];
            ldsm_x4(bh[0], bh[1], bh[2], bh[3], whb + off);
            ldsm_x4(bl[0], bl[1], bl[2], bl[3], wlb + off);
            mma_bf16(A.a[g][0], ahi, bh);        // hi*whi
            mma_bf16(A.a[g][1], ahi, bh + 2);
            mma_bf16(A.a[g][0], ahi, bl);        // hi*wlo
            mma_bf16(A.a[g][1], ahi, bl + 2);
            mma_bf16(A.a[g][0], alo, bh);        // lo*whi
            mma_bf16(A.a[g][1], alo, bh + 2);
        }
    }
}

__global__ void __launch_bounds__(512, 1) __cluster_dims__(4, 1, 1)
fused_persist(const float* __restrict__ h0,
              const float* __restrict__ x,
              const float* __restrict__ w_ih,
              const float* __restrict__ b_ih,
              const float* __restrict__ b_hh,
              const float* __restrict__ w1, const float* __restrict__ b1,
              const float* __restrict__ w2, const float* __restrict__ b2,
              const float* __restrict__ w3, const float* __restrict__ b3,
              float* __restrict__ out)
{
    extern __shared__ char smem[];
    const u32 sb = smem_u32(smem);
    const int tid  = threadIdx.x;

    // =====================================================================
    // GRU producer part (32 clusters; rank within cluster == jc)
    // =====================================================================
    if (blockIdx.x < NGRU) {
        float* sparam = (float*)(smem + SM_PRM);
        const int wid  = tid >> 5;
        const int lane = tid & 31;
        const int jc = blockIdx.x & 3;    // == %cluster_ctarank for (4,1,1)
        const int bg = blockIdx.x >> 2;
        const int j0 = jc * 64;
        const int b0 = bg * 64;
        const int wm = wid >> 2;
        const int wn = wid & 3;

        if (tid < 64) {
            int jg = j0 + tid;
            sparam[tid]        = w_ih[jg];
            sparam[64 + tid]   = w_ih[H + jg];
            sparam[128 + tid]  = w_ih[2 * H + jg];
            sparam[192 + tid]  = b_ih[jg]         + b_hh[jg];
            sparam[256 + tid]  = b_ih[H + jg]     + b_hh[H + jg];
            sparam[320 + tid]  = b_ih[2 * H + jg];
            sparam[384 + tid]  = b_hh[2 * H + jg];
        }

        // stage whi once (resident, SW128)
        for (int c = 0; c < 4; c++) {
            for (int f = tid; f < 192 * 8; f += 512) {
                int rr = f >> 3, cc = f & 7;
                int g = rr >> 6, jj = rr & 63;
                cp16(sb + SM_WHI + c * 24576 + rr * 128 + ((cc * 16) ^ ((rr & 7) << 4)),
                     g_whi + ((size_t)(g * H + j0 + jj)) * H + c * 64 + cc * 8);
            }
        }

        const int a_row  = lane & 15;
        const int a_colh = (lane >> 4) * 16;
        const int b_row  = ((lane >> 4) << 3) + (lane & 7);
        const int b_colh = ((lane >> 3) & 1) * 16;
        const int l4 = lane >> 2;
        const int lp = lane & 3;

        // register-resident h state for this lane's (b,j)
        float2 hst[2][2];
        #pragma unroll
        for (int e = 0; e < 2; e++)
            #pragma unroll
            for (int sub = 0; sub < 2; sub++) {
                int rowg = b0 + wm * 16 + l4 + 8 * e;
                int jl = wn * 16 + 8 * sub + 2 * lp;
                hst[e][sub] = *(const float2*)&h0[(size_t)rowg * H + j0 + jl];
            }

        // stage ALL 4 chunks of h0 locally (bf16 hi/lo, SW128)
        for (int f = tid; f < 64 * 128; f += 512) {
            int row = f >> 7;
            int kp  = f & 127;
            int c   = kp >> 5;
            int kpc = kp & 31;
            float2 hv = *(const float2*)&h0[(size_t)(b0 + row) * H + 2 * kp];
            __nv_bfloat162 h2 = __floats2bfloat162_rn(hv.x, hv.y);
            __nv_bfloat162 l2 = __floats2bfloat162_rn(hv.x - __bfloat162float(h2.x),
                                                      hv.y - __bfloat162float(h2.y));
            u32 off = (u32)(row * 128) + (u32)((kpc * 4) ^ ((row & 7) << 4));
            *(u32*)(smem + SM_A + c * 16384 + off)        = bf2u(h2);
            *(u32*)(smem + SM_A + c * 16384 + 8192 + off) = bf2u(l2);
        }
        cp_wait_all();
        __syncthreads();

        // sibling A-chunk bases (remote addr of MY chunk slot in THEIR smem)
        u32 rb[3];
        {
            u32 la = sb + SM_A + jc * 16384;
            int n = 0;
            #pragma unroll
            for (int r = 0; r < 4; r++)
                if (r != jc) rb[n++] = mapa_r(la, (u32)r);
        }

        // wlo staging helper indices
        #define STAGE_WLO(c, bufo)                                              \
            do {                                                                \
                _Pragma("unroll")                                               \
                for (int i_ = 0; i_ < 3; i_++) {                                \
                    int f_ = tid + i_ * 512;                                    \
                    int rr_ = f_ >> 3, cc_ = f_ & 7;                            \
                    int g_ = rr_ >> 6, jj_ = rr_ & 63;                          \
                    cp16(sb + SM_WLO + (bufo) + rr_ * 128 +                     \
                             ((cc_ * 16) ^ ((rr_ & 7) << 4)),                   \
                         g_wlo + ((size_t)(g_ * H + j0 + jj_)) * H +            \
                             (c) * 64 + cc_ * 8);                               \
                }                                                               \
            } while (0)

        // prefetch wlo chunks 0,1
        STAGE_WLO(0, 0);     cp_commit();
        STAGE_WLO(1, 24576); cp_commit();

        const u32 wlo0 = sb + SM_WLO;
        const u32 wlo1 = sb + SM_WLO + 24576;

        for (int t = 0; t < T; t++) {
            float xv0 = x[(size_t)t * B + b0 + wm * 16 + l4];
            float xv1 = x[(size_t)t * B + b0 + wm * 16 + l4 + 8];

            AccT A;
            #pragma unroll
            for (int g = 0; g < 3; g++)
                #pragma unroll
                for (int s = 0; s < 2; s++)
                    #pragma unroll
                    for (int q = 0; q < 4; q++) A.a[g][s][q] = 0.f;

            // chunk 0
            cp_wait_group<1>();
            __syncthreads();
            mma_section(A, sb + SM_A, sb + SM_WHI, wlo0,
                        wm, wn, a_row, a_colh, b_row, b_colh);
            // chunk 1
            cp_wait_group<0>();
            __syncthreads();
            STAGE_WLO(2, 0); cp_commit();
            mma_section(A, sb + SM_A + 16384, sb + SM_WHI + 24576, wlo1,
                        wm, wn, a_row, a_colh, b_row, b_colh);
            // chunk 2
            cp_wait_group<0>();
            __syncthreads();
            STAGE_WLO(3, 24576); cp_commit();
            mma_section(A, sb + SM_A + 32768, sb + SM_WHI + 49152, wlo0,
                        wm, wn, a_row, a_colh, b_row, b_colh);
            // chunk 3
            cp_wait_group<0>();
            __syncthreads();
            mma_section(A, sb + SM_A + 49152, sb + SM_WHI + 73728, wlo1,
                        wm, wn, a_row, a_colh, b_row, b_colh);

            if (t < T - 1) CLU_ARRIVE();   // phase 1: done reading h_{t-1}

            // epilogue: gates in regs; write global bf16 (for MLP); collect push payload
            u32 phi[4], plo[4], poff[4];
            int pi = 0;
            #pragma unroll
            for (int e = 0; e < 2; e++) {
                int rowl = wm * 16 + l4 + 8 * e;
                int rowg = b0 + rowl;
                float xv = e ? xv1 : xv0;
                #pragma unroll
                for (int sub = 0; sub < 2; sub++) {
                    int jl = wn * 16 + 8 * sub + 2 * lp;
                    float hn0, hn1;
                    {
                        int j = jl;
                        float r = fast_sigmoid(xv * sparam[j] + sparam[192 + j]
                                               + A.a[0][sub][e * 2]);
                        float z = fast_sigmoid(xv * sparam[64 + j] + sparam[256 + j]
                                               + A.a[1][sub][e * 2]);
                        float n = fast_tanh(xv * sparam[128 + j] + sparam[320 + j]
                                            + r * (A.a[2][sub][e * 2] + sparam[384 + j]));
                        hn0 = (1.f - z) * n + z * hst[e][sub].x;
                    }
                    {
                        int j = jl + 1;
                        float r = fast_sigmoid(xv * sparam[j] + sparam[192 + j]
                                               + A.a[0][sub][e * 2 + 1]);
                        float z = fast_sigmoid(xv * sparam[64 + j] + sparam[256 + j]
                                               + A.a[1][sub][e * 2 + 1]);
                        float n = fast_tanh(xv * sparam[128 + j] + sparam[320 + j]
                                            + r * (A.a[2][sub][e * 2 + 1] + sparam[384 + j]));
                        hn1 = (1.f - z) * n + z * hst[e][sub].y;
                    }
                    hst[e][sub] = make_float2(hn0, hn1);

                    __nv_bfloat162 h2 = __floats2bfloat162_rn(hn0, hn1);
                    __nv_bfloat162 l2 = __floats2bfloat162_rn(hn0 - __bfloat162float(h2.x),
                                                              hn1 - __bfloat162float(h2.y));
                    int kp = wn * 8 + 4 * sub + lp;
                    size_t gi = ((size_t)t * B + rowg) * 128 + jc * 32 + kp;
                    u32 uhi = bf2u(h2), ulo = bf2u(l2);
                    g_hhi[gi] = uhi;
                    g_hlo[gi] = ulo;
                    phi[pi] = uhi;
                    plo[pi] = ulo;
                    poff[pi] = (u32)(rowl * 128) + (u32)((kp * 4) ^ ((rowl & 7) << 4));
                    pi++;
                }
            }

            if (t < T - 1) {
                CLU_WAIT();   // phase 1 done: all CTAs finished reading A

                // push h_t chunk jc: local + 3 DSMEM siblings
                #pragma unroll
                for (int p = 0; p < 4; p++) {
                    *(u32*)(smem + SM_A + jc * 16384 + poff[p])        = phi[p];
                    *(u32*)(smem + SM_A + jc * 16384 + 8192 + poff[p]) = plo[p];
                    #pragma unroll
                    for (int s = 0; s < 3; s++) {
                        stc(rb[s] + poff[p], phi[p]);
                        stc(rb[s] + 8192 + poff[p], plo[p]);
                    }
                }
                CLU_ARRIVE();   // phase 2 arrive: my pushes released
            }

            // release h_t to MLP consumers (monotonic counter)
            __threadfence();
            __syncthreads();
            if (tid == 0) atomicAdd(&g_cnt[bg * 32], 1u);

            if (t < T - 1) {
                // re-prefetch wlo chunks 0,1 for next step (safe: post-sync)
                STAGE_WLO(0, 0);     cp_commit();
                STAGE_WLO(1, 24576); cp_commit();
                CLU_WAIT();   // phase 2 done: A holds full h_t
            }
        }
        #undef STAGE_WLO
        __syncthreads();
    }

    // =====================================================================
    // MLP consumer part (all blocks; queue-driven, gated on g_cnt)
    // =====================================================================
    {
        float* sm  = (float*)smem;
        float* xt  = sm;            // [64][256]
        float* w1s = sm + 16384;    // [64][260]
        float* h1s = sm + 33024;    // [64][64]
        float* h2t = sm + 37120;    // [64][66]
        float* w3s = sm;            // alias xt
        float* w2s = sm + 16384;    // alias w1s
        u32* qs = (u32*)(smem + SM_Q);

        const int jp = tid & 31;
        const int rg = (tid >> 5) & 7;
        const bool act = tid < 256;

        for (;;) {
            __syncthreads();
            if (tid == 0) *qs = atomicAdd(&g_q, 1u);
            __syncthreads();
            u32 q = *qs;
            if (q >= (u32)NTILE) break;
            int tt  = (int)(q >> 5);
            int bgq = (int)(q & 31);

            if (tid == 0) {
                u32 target = (u32)(4 * (tt + 1)), g;
                do {
                    asm volatile("ld.acquire.gpu.global.u32 %0, [%1];"
                                 : "=r"(g) : "l"(&g_cnt[bgq * 32]));
                } while ((int)(g - target) < 0);
            }
            __syncthreads();

            const size_t row0 = (size_t)q * RROWS;

            // reconstruct xt fp32 from bf16 hi/lo
            {
                const u32* hh = g_hhi + row0 * 128;
                const u32* ll = g_hlo + row0 * 128;
                for (int i = tid; i < RROWS * 128; i += 512) {
                    float2 a = u2f2(hh[i]);
                    float2 b = u2f2(ll[i]);
                    int row = i >> 7, kp = i & 127;
                    *(float2*)&xt[row * 256 + 2 * kp] = make_float2(a.x + b.x, a.y + b.y);
                }
            }
            for (int f = tid; f < H * H1; f += 512) {
                int jj = f & 63; int k = f >> 6;
                w1s[jj * 260 + k] = w1[f];
            }
            __syncthreads();

            // Stage 1
            if (act) {
                float acc[8][2];
                #pragma unroll
                for (int i = 0; i < 8; i++) { acc[i][0] = 0.f; acc[i][1] = 0.f; }
                #pragma unroll 4
                for (int k = 0; k < H; k += 4) {
                    float4 wa = *(const float4*)&w1s[(2 * jp) * 260 + k];
                    float4 wb = *(const float4*)&w1s[(2 * jp + 1) * 260 + k];
                    #pragma unroll
                    for (int i = 0; i < 8; i++) {
                        float4 xv = *(const float4*)&xt[(rg * 8 + i) * H + k];
                        acc[i][0] += xv.x * wa.x + xv.y * wa.y + xv.z * wa.z + xv.w * wa.w;
                        acc[i][1] += xv.x * wb.x + xv.y * wb.y + xv.z * wb.z + xv.w * wb.w;
                    }
                }
                float ba = b1[2 * jp], bb = b1[2 * jp + 1];
                #pragma unroll
                for (int i = 0; i < 8; i++) {
                    h1s[(rg * 8 + i) * 64 + 2 * jp]     = fast_elu(acc[i][0] + ba);
                    h1s[(rg * 8 + i) * 64 + 2 * jp + 1] = fast_elu(acc[i][1] + bb);
                }
            }
            __syncthreads();

            for (int f = tid; f < H1 * H2; f += 512) {
                int jj = f & 63; int k = f >> 6;
                w2s[jj * 68 + k] = w2[f];
            }
            __syncthreads();

            // Stage 2 (h2 transposed)
            if (act) {
                float acc[8][2];
                #pragma unroll
                for (int i = 0; i < 8; i++) { acc[i][0] = 0.f; acc[i][1] = 0.f; }
                #pragma unroll
                for (int k = 0; k < H1; k += 4) {
                    float4 wa = *(const float4*)&w2s[(2 * jp) * 68 + k];
                    float4 wb = *(const float4*)&w2s[(2 * jp + 1) * 68 + k];
                    #pragma unroll
                    for (int i = 0; i < 8; i++) {
                        float4 xv = *(const float4*)&h1s[(rg * 8 + i) * 64 + k];
                        acc[i][0] += xv.x * wa.x + xv.y * wa.y + xv.z * wa.z + xv.w * wa.w;
                        acc[i][1] += xv.x * wb.x + xv.y * wb.y + xv.z * wb.z + xv.w * wb.w;
                    }
                }
                float ba = b2[2 * jp], bb = b2[2 * jp + 1];
                #pragma unroll
                for (int i = 0; i < 8; i++) {
                    int row = rg * 8 + i;
                    h2t[(2 * jp) * 66 + row]     = fast_elu(acc[i][0] + ba);
                    h2t[(2 * jp + 1) * 66 + row] = fast_elu(acc[i][1] + bb);
                }
            }
            __syncthreads();

            // Stage 3: packed fp32x2 over row pairs
            for (int c0 = 0; c0 < OUTD; c0 += 128) {
                for (int f = tid; f < 64 * 128; f += 512) {
                    int c = f & 127; int k = f >> 7;
                    int cg = c0 + c;
                    w3s[k * 128 + c] = (cg < OUTD) ? w3[(size_t)k * OUTD + cg] : 0.f;
                }
                __syncthreads();

                if (act) {
                    u64 acc[4][4];
                    #pragma unroll
                    for (int rp = 0; rp < 4; rp++)
                        #pragma unroll
                        for (int qq = 0; qq < 4; qq++) acc[rp][qq] = 0ull;

                    #pragma unroll 4
                    for (int k = 0; k < H2; k++) {
                        u64 wd[4];
                        #pragma unroll
                        for (int qq = 0; qq < 4; qq++) {
                            float w = w3s[k * 128 + jp + 32 * qq];
                            wd[qq] = pack2(w, w);
                        }
                        const float* hp = &h2t[k * 66 + rg * 8];
                        u64 hv0 = *(const u64*)(hp + 0);
                        u64 hv1 = *(const u64*)(hp + 2);
                        u64 hv2 = *(const u64*)(hp + 4);
                        u64 hv3 = *(const u64*)(hp + 6);
                        #pragma unroll
                        for (int qq = 0; qq < 4; qq++) {
                            acc[0][qq] = ffma2(hv0, wd[qq], acc[0][qq]);
                            acc[1][qq] = ffma2(hv1, wd[qq], acc[1][qq]);
                            acc[2][qq] = ffma2(hv2, wd[qq], acc[2][qq]);
                            acc[3][qq] = ffma2(hv3, wd[qq], acc[3][qq]);
                        }
                    }

                    #pragma unroll
                    for (int qq = 0; qq < 4; qq++) {
                        int cg = c0 + jp + 32 * qq;
                        if (cg < OUTD) {
                            float bq = b3[cg];
                            #pragma unroll
                            for (int rp = 0; rp < 4; rp++) {
                                float2 v = unpack2(acc[rp][qq]);
                                size_t row = row0 + rg * 8 + 2 * rp;
                                out[row * OUTD + cg]       = v.x + bq;
                                out[(row + 1) * OUTD + cg] = v.y + bq;
                            }
                        }
                    }
                }
                __syncthreads();
            }
        }
    }
}

__global__ void copy_h_kernel(float* __restrict__ out)
{
    int i = blockIdx.x * blockDim.x + threadIdx.x;
    if (i < B * H / 2) {
        size_t base = (size_t)(T - 1) * B * 128;
        float2 a = u2f2(g_hhi[base + i]);
        float2 b = u2f2(g_hlo[base + i]);
        *(float2*)&out[2 * i] = make_float2(a.x + b.x, a.y + b.y);
    }
}

// ---------------------------------------------------------------------------
extern "C" void kernel_launch(void* const* d_in, const int* in_sizes, int n_in,
                              void* d_out, int out_size)
{
    const float* x    = (const float*)d_in[0];
    const float* h0   = (const float*)d_in[1];
    const float* w_ih = (const float*)d_in[2];
    const float* w_hh = (const float*)d_in[3];
    const float* b_ih = (const float*)d_in[4];
    const float* b_hh = (const float*)d_in[5];
    const float* w1   = (const float*)d_in[6];
    const float* b1   = (const float*)d_in[7];
    const float* w2   = (const float*)d_in[8];
    const float* b2   = (const float*)d_in[9];
    const float* w3   = (const float*)d_in[10];
    const float* b3   = (const float*)d_in[11];
    float* out = (float*)d_out;

    cudaFuncSetAttribute(fused_persist,
                         cudaFuncAttributeMaxDynamicSharedMemorySize, FUSED_SMEM);

    prep_w_kernel<<<(3 * H * H + 255) / 256, 256>>>(w_hh);

    fused_persist<<<GRID_P, 512, FUSED_SMEM>>>(h0, x, w_ih, b_ih, b_hh,
                                               w1, b1, w2, b2, w3, b3, out);

    copy_h_kernel<<<(B * H / 2 + 255) / 256, 256>>>(out + (size_t)T * B * OUTD);
}

// round 11
// speedup vs baseline: 1.2811x; 1.2811x over previous
#include <cuda_runtime.h>
#include <cuda_bf16.h>
#include <math.h>
#include <string.h>

typedef unsigned int u32;
typedef unsigned long long u64;

// ---------------------------------------------------------------------------
// Problem constants
// ---------------------------------------------------------------------------
constexpr int T    = 64;
constexpr int B    = 2048;
constexpr int H    = 256;
constexpr int H1   = 64;
constexpr int H2   = 64;
constexpr int OUTD = 601;
constexpr int RROWS = 64;
constexpr int NTILE = T * B / RROWS;   // 2048 MLP tiles

// ---------------------------------------------------------------------------
// PTX helpers
// ---------------------------------------------------------------------------
__device__ __forceinline__ u32 smem_u32(const void* p) {
    u32 a;
    asm("{ .reg .u64 t; cvta.to.shared.u64 t, %1; cvt.u32.u64 %0, t; }"
        : "=r"(a) : "l"(p));
    return a;
}
__device__ __forceinline__ void ldsm_x4(u32& r0, u32& r1, u32& r2, u32& r3, u32 addr) {
    asm volatile("ldmatrix.sync.aligned.m8n8.x4.shared.b16 {%0,%1,%2,%3}, [%4];"
                 : "=r"(r0), "=r"(r1), "=r"(r2), "=r"(r3) : "r"(addr));
}
__device__ __forceinline__ void mma_bf16(float* d, const u32* a, const u32* b) {
    asm volatile(
        "mma.sync.aligned.m16n8k16.row.col.f32.bf16.bf16.f32 "
        "{%0,%1,%2,%3}, {%4,%5,%6,%7}, {%8,%9}, {%0,%1,%2,%3};"
        : "+f"(d[0]), "+f"(d[1]), "+f"(d[2]), "+f"(d[3])
        : "r"(a[0]), "r"(a[1]), "r"(a[2]), "r"(a[3]), "r"(b[0]), "r"(b[1]));
}
__device__ __forceinline__ void cp16(u32 dst, const void* src) {
    asm volatile("cp.async.ca.shared.global [%0], [%1], 16;" :: "r"(dst), "l"(src));
}
__device__ __forceinline__ void cp_commit() {
    asm volatile("cp.async.commit_group;" ::: "memory");
}
template <int N>
__device__ __forceinline__ void cp_wait_group() {
    asm volatile("cp.async.wait_group %0;" :: "n"(N) : "memory");
}
__device__ __forceinline__ void cp_wait_all() {
    asm volatile("cp.async.wait_all;" ::: "memory");
}
__device__ __forceinline__ u32 bf2u(__nv_bfloat162 v) {
    u32 r; memcpy(&r, &v, 4); return r;
}
__device__ __forceinline__ float2 u2f2(u32 v) {
    __nv_bfloat162 b; memcpy(&b, &v, 4);
    return make_float2(__bfloat162float(b.x), __bfloat162float(b.y));
}
__device__ __forceinline__ u64 ffma2(u64 a, u64 b, u64 c) {
    u64 d; asm("fma.rn.f32x2 %0, %1, %2, %3;" : "=l"(d) : "l"(a), "l"(b), "l"(c));
    return d;
}
__device__ __forceinline__ u64 pack2(float x, float y) {
    u64 d; asm("mov.b64 %0, {%1, %2};" : "=l"(d) : "f"(x), "f"(y));
    return d;
}
__device__ __forceinline__ float2 unpack2(u64 v) {
    float2 r; asm("mov.b64 {%0, %1}, %2;" : "=f"(r.x), "=f"(r.y) : "l"(v));
    return r;
}
constexpr float LOG2E = 1.4426950408889634f;
__device__ __forceinline__ float fast_sigmoid(float v) {
    float e; asm("ex2.approx.f32 %0, %1;" : "=f"(e) : "f"(-LOG2E * v));
    float r; asm("rcp.approx.f32 %0, %1;" : "=f"(r) : "f"(1.f + e));
    return r;
}
__device__ __forceinline__ float fast_tanh(float v) {
    float e; asm("ex2.approx.f32 %0, %1;" : "=f"(e) : "f"(2.f * LOG2E * v));
    float r; asm("rcp.approx.f32 %0, %1;" : "=f"(r) : "f"(1.f + e));
    return 1.f - 2.f * r;
}
__device__ __forceinline__ float fast_elu(float v) {
    if (v > 0.f) return v;
    float e; asm("ex2.approx.f32 %0, %1;" : "=f"(e) : "f"(LOG2E * v));
    return e - 1.f;
}

// ---------------------------------------------------------------------------
// Device scratch: h stored ONLY as t-indexed bf16 hi/lo
// ---------------------------------------------------------------------------
__device__ u32 g_hhi[(size_t)T * B * (H / 2)];   // [t][b][kp] bf16x2 hi
__device__ u32 g_hlo[(size_t)T * B * (H / 2)];   // [t][b][kp] bf16x2 lo
__device__ __nv_bfloat16 g_whi[(size_t)3 * H * H];
__device__ __nv_bfloat16 g_wlo[(size_t)3 * H * H];
__device__ u32 g_cnt[32 * 32];    // per-bg monotonic counters (128B apart)
__device__ u32 g_q;               // MLP tile queue

__global__ void prep_w_kernel(const float* __restrict__ w_hh)
{
    int i = blockIdx.x * blockDim.x + threadIdx.x;
    if (i < 3 * H * H) {
        float w = w_hh[i];
        __nv_bfloat16 hi = __float2bfloat16(w);
        g_whi[i] = hi;
        g_wlo[i] = __float2bfloat16(w - __bfloat162float(hi));
    }
    if (blockIdx.x == 0 && threadIdx.x < 32) {
        g_cnt[threadIdx.x * 32] = 0;
        if (threadIdx.x == 0) g_q = 0;
    }
}

// ---------------------------------------------------------------------------
// Fused persistent kernel: 148 blocks x 512 threads.
// GRU (blocks 0..127): 8 MMA warps (m32 x n48 tiles) + 8 staging warps that
// poll/stage h chunks concurrently. Blocks 128..147 + finished GRU blocks:
// MLP consumers from a tile queue gated on g_cnt.
// ---------------------------------------------------------------------------
constexpr int GRID_P = 148;
constexpr int NGRU   = 128;
constexpr int SM_W      = 0;        // whi [4][192][128B]=98304 ; wlo at +98304
constexpr int SM_WLO_O  = 98304;
constexpr int SM_A      = 196608;   // 2 bufs x (hi 8192 + lo 8192)
constexpr int SM_PRM    = 229376;   // 7*64 f32 = 1792B
constexpr int SM_Q      = 231168;   // queue broadcast slot
constexpr int FUSED_SMEM = 231296;

struct AccT { float a[2][3][2][4]; };   // [mt][gate][sub][q]

__device__ __forceinline__ void mma_section32(AccT& A, u32 ab, u32 wb,
                                              int wm, int wn,
                                              int a_row, int a_colh,
                                              int b_row, int b_colh)
{
    #pragma unroll
    for (int ks = 0; ks < 4; ks++) {
        u32 ahi[2][4], alo[2][4];
        #pragma unroll
        for (int mt = 0; mt < 2; mt++) {
            int r = wm * 32 + mt * 16 + a_row;
            u32 off = (u32)(r * 128) + (u32)((ks * 32 + a_colh) ^ ((r & 7) << 4));
            ldsm_x4(ahi[mt][0], ahi[mt][1], ahi[mt][2], ahi[mt][3], ab + off);
            ldsm_x4(alo[mt][0], alo[mt][1], alo[mt][2], alo[mt][3], ab + 8192 + off);
        }
        #pragma unroll
        for (int g = 0; g < 3; g++) {
            int rr = g * 64 + wn * 16 + b_row;
            u32 off = (u32)(rr * 128) + (u32)((ks * 32 + b_colh) ^ ((rr & 7) << 4));
            u32 bh[4], bl[4];
            ldsm_x4(bh[0], bh[1], bh[2], bh[3], wb + off);
            ldsm_x4(bl[0], bl[1], bl[2], bl[3], wb + SM_WLO_O + off);
            #pragma unroll
            for (int mt = 0; mt < 2; mt++) {
                mma_bf16(A.a[mt][g][0], ahi[mt], bh);        // hi*whi
                mma_bf16(A.a[mt][g][1], ahi[mt], bh + 2);
                mma_bf16(A.a[mt][g][0], ahi[mt], bl);        // hi*wlo
                mma_bf16(A.a[mt][g][1], ahi[mt], bl + 2);
                mma_bf16(A.a[mt][g][0], alo[mt], bh);        // lo*whi
                mma_bf16(A.a[mt][g][1], alo[mt], bh + 2);
            }
        }
    }
}

__global__ void __launch_bounds__(512, 1)
fused_persist(const float* __restrict__ h0,
              const float* __restrict__ x,
              const float* __restrict__ w_ih,
              const float* __restrict__ b_ih,
              const float* __restrict__ b_hh,
              const float* __restrict__ w1, const float* __restrict__ b1,
              const float* __restrict__ w2, const float* __restrict__ b2,
              const float* __restrict__ w3, const float* __restrict__ b3,
              float* __restrict__ out)
{
    extern __shared__ char smem[];
    const u32 sb = smem_u32(smem);
    const int tid  = threadIdx.x;

    // =====================================================================
    // GRU producer part
    // =====================================================================
    if (blockIdx.x < NGRU) {
        float* sparam = (float*)(smem + SM_PRM);
        const int wid  = tid >> 5;
        const int lane = tid & 31;
        const int jc = blockIdx.x & 3;
        const int bg = blockIdx.x >> 2;
        const int j0 = jc * 64;
        const int b0 = bg * 64;
        const bool mmaw = wid < 8;
        const int wm = (wid >> 2) & 1;   // 0..1 (32 rows each)
        const int wn = wid & 3;          // 0..3 (16 j-cols x 3 gates)
        const int stid = tid - 256;      // staging-warp linear id (0..255)

        if (tid < 64) {
            int jg = j0 + tid;
            sparam[tid]        = w_ih[jg];
            sparam[64 + tid]   = w_ih[H + jg];
            sparam[128 + tid]  = w_ih[2 * H + jg];
            sparam[192 + tid]  = b_ih[jg]         + b_hh[jg];
            sparam[256 + tid]  = b_ih[H + jg]     + b_hh[H + jg];
            sparam[320 + tid]  = b_ih[2 * H + jg];
            sparam[384 + tid]  = b_hh[2 * H + jg];
        }

        // stage all weights once (bf16 hi/lo, SW128, resident)
        for (int c = 0; c < 4; c++) {
            for (int f = tid; f < 192 * 8; f += 512) {
                int rr = f >> 3, cc = f & 7;
                int g = rr >> 6, jj = rr & 63;
                size_t src = ((size_t)(g * H + j0 + jj)) * H + c * 64 + cc * 8;
                u32 d = sb + SM_W + c * 24576 + rr * 128 + ((cc * 16) ^ ((rr & 7) << 4));
                cp16(d, g_whi + src);
                cp16(d + SM_WLO_O, g_wlo + src);
            }
        }

        const int a_row  = lane & 15;
        const int a_colh = (lane >> 4) * 16;
        const int b_row  = ((lane >> 4) << 3) + (lane & 7);
        const int b_colh = ((lane >> 3) & 1) * 16;
        const int l4 = lane >> 2;
        const int lp = lane & 3;

        // register-resident h state (MMA warps): e in 0..3 -> rows wm*32+(e>>1)*16+(e&1)*8+l4
        float2 hst[4][2];
        if (mmaw) {
            #pragma unroll
            for (int e = 0; e < 4; e++)
                #pragma unroll
                for (int sub = 0; sub < 2; sub++) {
                    int rowg = b0 + wm * 32 + (e >> 1) * 16 + (e & 1) * 8 + l4;
                    int jl = wn * 16 + 8 * sub + 2 * lp;
                    hst[e][sub] = *(const float2*)&h0[(size_t)rowg * H + j0 + jl];
                }
        }

        // pre-stage OWN chunk (jc) of h0 into buf0 (all threads)
        #pragma unroll
        for (int i = 0; i < 4; i++) {
            int f = tid + i * 512;
            int row = f >> 5, kp = f & 31;
            float2 hv = *(const float2*)&h0[(size_t)(b0 + row) * H + jc * 64 + 2 * kp];
            __nv_bfloat162 h2 = __floats2bfloat162_rn(hv.x, hv.y);
            __nv_bfloat162 l2 = __floats2bfloat162_rn(hv.x - __bfloat162float(h2.x),
                                                      hv.y - __bfloat162float(h2.y));
            u32 off = (u32)(row * 128) + (u32)((kp * 4) ^ ((row & 7) << 4));
            *(u32*)(smem + SM_A + off)        = bf2u(h2);
            *(u32*)(smem + SM_A + 8192 + off) = bf2u(l2);
        }
        cp_wait_all();
        __syncthreads();

        const u32 ab0 = sb + SM_A;
        const u32 ab1 = sb + SM_A + 16384;
        const int c1 = (jc + 1) & 3, c2 = (jc + 2) & 3, c3 = (jc + 3) & 3;

        // staging helpers (staging warps only; stid in 0..255)
        #define STAGE_CP(c, dst)                                                 \
            do {                                                                 \
                size_t base_ = ((size_t)(t - 1) * B + b0) * 128 + (size_t)(c) * 32; \
                _Pragma("unroll")                                                \
                for (int i_ = 0; i_ < 2; i_++) {                                 \
                    int f_ = stid + i_ * 256;                                    \
                    int rr_ = f_ >> 3, cc_ = f_ & 7;                             \
                    u32 o_ = (u32)(rr_ * 128) + (u32)((cc_ * 16) ^ ((rr_ & 7) << 4)); \
                    cp16((dst) + o_,        &g_hhi[base_ + (size_t)rr_ * 128 + cc_ * 4]); \
                    cp16((dst) + 8192 + o_, &g_hlo[base_ + (size_t)rr_ * 128 + cc_ * 4]); \
                }                                                                \
                cp_commit();                                                     \
                cp_wait_group<0>();                                              \
            } while (0)

        #define STAGE_CVT(c, dstc)                                               \
            do {                                                                 \
                _Pragma("unroll")                                                \
                for (int i_ = 0; i_ < 8; i_++) {                                 \
                    int f_ = stid + i_ * 256;                                    \
                    int row_ = f_ >> 5, kp_ = f_ & 31;                           \
                    float2 hv_ = *(const float2*)&h0[(size_t)(b0 + row_) * H + (c) * 64 + 2 * kp_]; \
                    __nv_bfloat162 h2_ = __floats2bfloat162_rn(hv_.x, hv_.y);    \
                    __nv_bfloat162 l2_ = __floats2bfloat162_rn(                  \
                        hv_.x - __bfloat162float(h2_.x),                         \
                        hv_.y - __bfloat162float(h2_.y));                        \
                    u32 o_ = (u32)(row_ * 128) + (u32)((kp_ * 4) ^ ((row_ & 7) << 4)); \
                    *(u32*)((dstc) + o_)        = bf2u(h2_);                     \
                    *(u32*)((dstc) + 8192 + o_) = bf2u(l2_);                     \
                }                                                                \
            } while (0)

        for (int t = 0; t < T; t++) {
            AccT A;
            float xvv[4];

            // ---- phase 0: MMA on own chunk; staging polls + stages c1 ----
            if (mmaw) {
                #pragma unroll
                for (int mt = 0; mt < 2; mt++)
                    #pragma unroll
                    for (int g = 0; g < 3; g++)
                        #pragma unroll
                        for (int s = 0; s < 2; s++)
                            #pragma unroll
                            for (int q = 0; q < 4; q++) A.a[mt][g][s][q] = 0.f;
                #pragma unroll
                for (int e = 0; e < 4; e++)
                    xvv[e] = x[(size_t)t * B + b0 + wm * 32 + (e >> 1) * 16
                               + (e & 1) * 8 + l4];
                mma_section32(A, ab0, sb + SM_W + jc * 24576,
                              wm, wn, a_row, a_colh, b_row, b_colh);
            } else {
                if (t > 0) {
                    if (lane == 0) {
                        u32 g;
                        do {
                            asm volatile("ld.acquire.gpu.global.u32 %0, [%1];"
                                         : "=r"(g) : "l"(&g_cnt[bg * 32]));
                        } while ((int)(g - (u32)(4 * t)) < 0);
                    }
                    __syncwarp();
                    STAGE_CP(c1, ab1);
                } else {
                    STAGE_CVT(c1, smem + SM_A + 16384);
                }
            }
            __syncthreads();

            // ---- phase 1: MMA c1 (buf1); staging stages c2 -> buf0 ----
            if (mmaw) {
                mma_section32(A, ab1, sb + SM_W + c1 * 24576,
                              wm, wn, a_row, a_colh, b_row, b_colh);
            } else {
                if (t > 0) STAGE_CP(c2, ab0);
                else       STAGE_CVT(c2, smem + SM_A);
            }
            __syncthreads();

            // ---- phase 2: MMA c2 (buf0); staging stages c3 -> buf1 ----
            if (mmaw) {
                mma_section32(A, ab0, sb + SM_W + c2 * 24576,
                              wm, wn, a_row, a_colh, b_row, b_colh);
            } else {
                if (t > 0) STAGE_CP(c3, ab1);
                else       STAGE_CVT(c3, smem + SM_A + 16384);
            }
            __syncthreads();

            // ---- phase 3: MMA c3 (buf1); epilogue ----
            if (mmaw) {
                mma_section32(A, ab1, sb + SM_W + c3 * 24576,
                              wm, wn, a_row, a_colh, b_row, b_colh);

                #pragma unroll
                for (int mt = 0; mt < 2; mt++)
                    #pragma unroll
                    for (int half = 0; half < 2; half++) {
                        int e = mt * 2 + half;
                        int rowl = wm * 32 + mt * 16 + half * 8 + l4;
                        int rowg = b0 + rowl;
                        float xv = xvv[e];
                        #pragma unroll
                        for (int sub = 0; sub < 2; sub++) {
                            int jl = wn * 16 + 8 * sub + 2 * lp;
                            float hn0, hn1;
                            {
                                int j = jl;
                                float r = fast_sigmoid(xv * sparam[j] + sparam[192 + j]
                                                       + A.a[mt][0][sub][half * 2]);
                                float z = fast_sigmoid(xv * sparam[64 + j] + sparam[256 + j]
                                                       + A.a[mt][1][sub][half * 2]);
                                float n = fast_tanh(xv * sparam[128 + j] + sparam[320 + j]
                                                    + r * (A.a[mt][2][sub][half * 2]
                                                           + sparam[384 + j]));
                                hn0 = (1.f - z) * n + z * hst[e][sub].x;
                            }
                            {
                                int j = jl + 1;
                                float r = fast_sigmoid(xv * sparam[j] + sparam[192 + j]
                                                       + A.a[mt][0][sub][half * 2 + 1]);
                                float z = fast_sigmoid(xv * sparam[64 + j] + sparam[256 + j]
                                                       + A.a[mt][1][sub][half * 2 + 1]);
                                float n = fast_tanh(xv * sparam[128 + j] + sparam[320 + j]
                                                    + r * (A.a[mt][2][sub][half * 2 + 1]
                                                           + sparam[384 + j]));
                                hn1 = (1.f - z) * n + z * hst[e][sub].y;
                            }
                            hst[e][sub] = make_float2(hn0, hn1);

                            __nv_bfloat162 h2 = __floats2bfloat162_rn(hn0, hn1);
                            __nv_bfloat162 l2 = __floats2bfloat162_rn(
                                hn0 - __bfloat162float(h2.x),
                                hn1 - __bfloat162float(h2.y));
                            int kp = wn * 8 + 4 * sub + lp;
                            size_t gi = ((size_t)t * B + rowg) * 128 + jc * 32 + kp;
                            u32 uhi = bf2u(h2), ulo = bf2u(l2);
                            g_hhi[gi] = uhi;
                            g_hlo[gi] = ulo;
                            // own chunk straight into buf0 for next step
                            u32 off = (u32)(rowl * 128)
                                      + (u32)((kp * 4) ^ ((rowl & 7) << 4));
                            *(u32*)(smem + SM_A + off)        = uhi;
                            *(u32*)(smem + SM_A + 8192 + off) = ulo;
                        }
                    }
            }

            // ---- release h_t (monotonic) ----
            __threadfence();
            __syncthreads();
            if (tid == 0) atomicAdd(&g_cnt[bg * 32], 1u);
        }
        #undef STAGE_CP
        #undef STAGE_CVT
        __syncthreads();
    }

    // =====================================================================
    // MLP consumer part (all blocks; queue-driven, gated on g_cnt)
    // =====================================================================
    {
        float* sm  = (float*)smem;
        float* xt  = sm;            // [64][256]
        float* w1s = sm + 16384;    // [64][260]
        float* h1s = sm + 33024;    // [64][64]
        float* h2t = sm + 37120;    // [64][66]
        float* w3s = sm;            // alias xt
        float* w2s = sm + 16384;    // alias w1s
        u32* qs = (u32*)(smem + SM_Q);

        const int jp = tid & 31;
        const int rg = (tid >> 5) & 7;
        const bool act = tid < 256;

        for (;;) {
            __syncthreads();
            if (tid == 0) *qs = atomicAdd(&g_q, 1u);
            __syncthreads();
            u32 q = *qs;
            if (q >= (u32)NTILE) break;
            int tt  = (int)(q >> 5);
            int bgq = (int)(q & 31);

            if (tid == 0) {
                u32 target = (u32)(4 * (tt + 1)), g;
                do {
                    asm volatile("ld.acquire.gpu.global.u32 %0, [%1];"
                                 : "=r"(g) : "l"(&g_cnt[bgq * 32]));
                } while ((int)(g - target) < 0);
            }
            __syncthreads();

            const size_t row0 = (size_t)q * RROWS;

            // reconstruct xt fp32 from bf16 hi/lo
            {
                const u32* hh = g_hhi + row0 * 128;
                const u32* ll = g_hlo + row0 * 128;
                for (int i = tid; i < RROWS * 128; i += 512) {
                    float2 a = u2f2(hh[i]);
                    float2 b = u2f2(ll[i]);
                    int row = i >> 7, kp = i & 127;
                    *(float2*)&xt[row * 256 + 2 * kp] = make_float2(a.x + b.x, a.y + b.y);
                }
            }
            for (int f = tid; f < H * H1; f += 512) {
                int jj = f & 63; int k = f >> 6;
                w1s[jj * 260 + k] = w1[f];
            }
            __syncthreads();

            // Stage 1
            if (act) {
                float acc[8][2];
                #pragma unroll
                for (int i = 0; i < 8; i++) { acc[i][0] = 0.f; acc[i][1] = 0.f; }
                #pragma unroll 4
                for (int k = 0; k < H; k += 4) {
                    float4 wa = *(const float4*)&w1s[(2 * jp) * 260 + k];
                    float4 wb = *(const float4*)&w1s[(2 * jp + 1) * 260 + k];
                    #pragma unroll
                    for (int i = 0; i < 8; i++) {
                        float4 xv = *(const float4*)&xt[(rg * 8 + i) * H + k];
                        acc[i][0] += xv.x * wa.x + xv.y * wa.y + xv.z * wa.z + xv.w * wa.w;
                        acc[i][1] += xv.x * wb.x + xv.y * wb.y + xv.z * wb.z + xv.w * wb.w;
                    }
                }
                float ba = b1[2 * jp], bb = b1[2 * jp + 1];
                #pragma unroll
                for (int i = 0; i < 8; i++) {
                    h1s[(rg * 8 + i) * 64 + 2 * jp]     = fast_elu(acc[i][0] + ba);
                    h1s[(rg * 8 + i) * 64 + 2 * jp + 1] = fast_elu(acc[i][1] + bb);
                }
            }
            __syncthreads();

            for (int f = tid; f < H1 * H2; f += 512) {
                int jj = f & 63; int k = f >> 6;
                w2s[jj * 68 + k] = w2[f];
            }
            __syncthreads();

            // Stage 2 (h2 transposed)
            if (act) {
                float acc[8][2];
                #pragma unroll
                for (int i = 0; i < 8; i++) { acc[i][0] = 0.f; acc[i][1] = 0.f; }
                #pragma unroll
                for (int k = 0; k < H1; k += 4) {
                    float4 wa = *(const float4*)&w2s[(2 * jp) * 68 + k];
                    float4 wb = *(const float4*)&w2s[(2 * jp + 1) * 68 + k];
                    #pragma unroll
                    for (int i = 0; i < 8; i++) {
                        float4 xv = *(const float4*)&h1s[(rg * 8 + i) * 64 + k];
                        acc[i][0] += xv.x * wa.x + xv.y * wa.y + xv.z * wa.z + xv.w * wa.w;
                        acc[i][1] += xv.x * wb.x + xv.y * wb.y + xv.z * wb.z + xv.w * wb.w;
                    }
                }
                float ba = b2[2 * jp], bb = b2[2 * jp + 1];
                #pragma unroll
                for (int i = 0; i < 8; i++) {
                    int row = rg * 8 + i;
                    h2t[(2 * jp) * 66 + row]     = fast_elu(acc[i][0] + ba);
                    h2t[(2 * jp + 1) * 66 + row] = fast_elu(acc[i][1] + bb);
                }
            }
            __syncthreads();

            // Stage 3: packed fp32x2 over row pairs
            for (int c0 = 0; c0 < OUTD; c0 += 128) {
                for (int f = tid; f < 64 * 128; f += 512) {
                    int c = f & 127; int k = f >> 7;
                    int cg = c0 + c;
                    w3s[k * 128 + c] = (cg < OUTD) ? w3[(size_t)k * OUTD + cg] : 0.f;
                }
                __syncthreads();

                if (act) {
                    u64 acc[4][4];
                    #pragma unroll
                    for (int rp = 0; rp < 4; rp++)
                        #pragma unroll
                        for (int qq = 0; qq < 4; qq++) acc[rp][qq] = 0ull;

                    #pragma unroll 4
                    for (int k = 0; k < H2; k++) {
                        u64 wd[4];
                        #pragma unroll
                        for (int qq = 0; qq < 4; qq++) {
                            float w = w3s[k * 128 + jp + 32 * qq];
                            wd[qq] = pack2(w, w);
                        }
                        const float* hp = &h2t[k * 66 + rg * 8];
                        u64 hv0 = *(const u64*)(hp + 0);
                        u64 hv1 = *(const u64*)(hp + 2);
                        u64 hv2 = *(const u64*)(hp + 4);
                        u64 hv3 = *(const u64*)(hp + 6);
                        #pragma unroll
                        for (int qq = 0; qq < 4; qq++) {
                            acc[0][qq] = ffma2(hv0, wd[qq], acc[0][qq]);
                            acc[1][qq] = ffma2(hv1, wd[qq], acc[1][qq]);
                            acc[2][qq] = ffma2(hv2, wd[qq], acc[2][qq]);
                            acc[3][qq] = ffma2(hv3, wd[qq], acc[3][qq]);
                        }
                    }

                    #pragma unroll
                    for (int qq = 0; qq < 4; qq++) {
                        int cg = c0 + jp + 32 * qq;
                        if (cg < OUTD) {
                            float bq = b3[cg];
                            #pragma unroll
                            for (int rp = 0; rp < 4; rp++) {
                                float2 v = unpack2(acc[rp][qq]);
                                size_t row = row0 + rg * 8 + 2 * rp;
                                out[row * OUTD + cg]       = v.x + bq;
                                out[(row + 1) * OUTD + cg] = v.y + bq;
                            }
                        }
                    }
                }
                __syncthreads();
            }
        }
    }
}

__global__ void copy_h_kernel(float* __restrict__ out)
{
    int i = blockIdx.x * blockDim.x + threadIdx.x;
    if (i < B * H / 2) {
        size_t base = (size_t)(T - 1) * B * 128;
        float2 a = u2f2(g_hhi[base + i]);
        float2 b = u2f2(g_hlo[base + i]);
        *(float2*)&out[2 * i] = make_float2(a.x + b.x, a.y + b.y);
    }
}

// ---------------------------------------------------------------------------
extern "C" void kernel_launch(void* const* d_in, const int* in_sizes, int n_in,
                              void* d_out, int out_size)
{
    const float* x    = (const float*)d_in[0];
    const float* h0   = (const float*)d_in[1];
    const float* w_ih = (const float*)d_in[2];
    const float* w_hh = (const float*)d_in[3];
    const float* b_ih = (const float*)d_in[4];
    const float* b_hh = (const float*)d_in[5];
    const float* w1   = (const float*)d_in[6];
    const float* b1   = (const float*)d_in[7];
    const float* w2   = (const float*)d_in[8];
    const float* b2   = (const float*)d_in[9];
    const float* w3   = (const float*)d_in[10];
    const float* b3   = (const float*)d_in[11];
    float* out = (float*)d_out;

    cudaFuncSetAttribute(fused_persist,
                         cudaFuncAttributeMaxDynamicSharedMemorySize, FUSED_SMEM);

    prep_w_kernel<<<(3 * H * H + 255) / 256, 256>>>(w_hh);

    fused_persist<<<GRID_P, 512, FUSED_SMEM>>>(h0, x, w_ih, b_ih, b_hh,
                                               w1, b1, w2, b2, w3, b3, out);

    copy_h_kernel<<<(B * H / 2 + 255) / 256, 256>>>(out + (size_t)T * B * OUTD);
}

// round 12
// speedup vs baseline: 1.2820x; 1.0007x over previous
#include <cuda_runtime.h>
#include <cuda_bf16.h>
#include <math.h>
#include <string.h>

typedef unsigned int u32;
typedef unsigned long long u64;

// ---------------------------------------------------------------------------
// Problem constants
// ---------------------------------------------------------------------------
constexpr int T    = 64;
constexpr int B    = 2048;
constexpr int H    = 256;
constexpr int H1   = 64;
constexpr int H2   = 64;
constexpr int OUTD = 601;
constexpr int RROWS = 64;
constexpr int NTILE = T * B / RROWS;      // 2048 MLP tiles
constexpr int NCOPY = 8;                  // h_last copy tiles (256 rows each)
constexpr int NTILE_TOT = NTILE + NCOPY;  // 2056

// ---------------------------------------------------------------------------
// PTX helpers
// ---------------------------------------------------------------------------
__device__ __forceinline__ u32 smem_u32(const void* p) {
    u32 a;
    asm("{ .reg .u64 t; cvta.to.shared.u64 t, %1; cvt.u32.u64 %0, t; }"
        : "=r"(a) : "l"(p));
    return a;
}
__device__ __forceinline__ void ldsm_x4(u32& r0, u32& r1, u32& r2, u32& r3, u32 addr) {
    asm volatile("ldmatrix.sync.aligned.m8n8.x4.shared.b16 {%0,%1,%2,%3}, [%4];"
                 : "=r"(r0), "=r"(r1), "=r"(r2), "=r"(r3) : "r"(addr));
}
__device__ __forceinline__ void mma_bf16(float* d, const u32* a, const u32* b) {
    asm volatile(
        "mma.sync.aligned.m16n8k16.row.col.f32.bf16.bf16.f32 "
        "{%0,%1,%2,%3}, {%4,%5,%6,%7}, {%8,%9}, {%0,%1,%2,%3};"
        : "+f"(d[0]), "+f"(d[1]), "+f"(d[2]), "+f"(d[3])
        : "r"(a[0]), "r"(a[1]), "r"(a[2]), "r"(a[3]), "r"(b[0]), "r"(b[1]));
}
__device__ __forceinline__ void cp16(u32 dst, const void* src) {
    asm volatile("cp.async.ca.shared.global [%0], [%1], 16;" :: "r"(dst), "l"(src));
}
__device__ __forceinline__ void cp_commit() {
    asm volatile("cp.async.commit_group;" ::: "memory");
}
template <int N>
__device__ __forceinline__ void cp_wait_group() {
    asm volatile("cp.async.wait_group %0;" :: "n"(N) : "memory");
}
__device__ __forceinline__ u32 bf2u(__nv_bfloat162 v) {
    u32 r; memcpy(&r, &v, 4); return r;
}
__device__ __forceinline__ float2 u2f2(u32 v) {
    __nv_bfloat162 b; memcpy(&b, &v, 4);
    return make_float2(__bfloat162float(b.x), __bfloat162float(b.y));
}
__device__ __forceinline__ u64 ffma2(u64 a, u64 b, u64 c) {
    u64 d; asm("fma.rn.f32x2 %0, %1, %2, %3;" : "=l"(d) : "l"(a), "l"(b), "l"(c));
    return d;
}
__device__ __forceinline__ u64 pack2(float x, float y) {
    u64 d; asm("mov.b64 %0, {%1, %2};" : "=l"(d) : "f"(x), "f"(y));
    return d;
}
__device__ __forceinline__ float2 unpack2(u64 v) {
    float2 r; asm("mov.b64 {%0, %1}, %2;" : "=f"(r.x), "=f"(r.y) : "l"(v));
    return r;
}
constexpr float LOG2E = 1.4426950408889634f;
__device__ __forceinline__ float fast_sigmoid(float v) {
    float e; asm("ex2.approx.f32 %0, %1;" : "=f"(e) : "f"(-LOG2E * v));
    float r; asm("rcp.approx.f32 %0, %1;" : "=f"(r) : "f"(1.f + e));
    return r;
}
__device__ __forceinline__ float fast_tanh(float v) {
    float e; asm("ex2.approx.f32 %0, %1;" : "=f"(e) : "f"(2.f * LOG2E * v));
    float r; asm("rcp.approx.f32 %0, %1;" : "=f"(r) : "f"(1.f + e));
    return 1.f - 2.f * r;
}
__device__ __forceinline__ float fast_elu(float v) {
    if (v > 0.f) return v;
    float e; asm("ex2.approx.f32 %0, %1;" : "=f"(e) : "f"(LOG2E * v));
    return e - 1.f;
}

// ---------------------------------------------------------------------------
// Device scratch: h stored ONLY as t-indexed bf16 hi/lo
// ---------------------------------------------------------------------------
__device__ u32 g_hhi[(size_t)T * B * (H / 2)];   // [t][b][kp] bf16x2 hi
__device__ u32 g_hlo[(size_t)T * B * (H / 2)];   // [t][b][kp] bf16x2 lo
__device__ u32 g_cnt[32 * 32] = {};  // per-bg monotonic counters (128B apart)
__device__ u32 g_q = 0;              // work queue (MLP tiles + copy tiles)

// ---------------------------------------------------------------------------
// Single fused persistent kernel: 148 blocks x 512 threads.
// GRU (blocks 0..127): inline weight split; 8 MMA warps (m32 x n48) + 8
// staging warps. All blocks then consume from a queue: 2048 MLP tiles +
// 8 h_last copy tiles. The block drawing the LAST exit-pop resets the
// synchronization state for the next graph replay.
// ---------------------------------------------------------------------------
constexpr int GRID_P = 148;
constexpr int NGRU   = 128;
constexpr int SM_W      = 0;        // whi [4][192][128B]=98304 ; wlo at +98304
constexpr int SM_WLO_O  = 98304;
constexpr int SM_A      = 196608;   // 2 bufs x (hi 8192 + lo 8192)
constexpr int SM_PRM    = 229376;   // 7*64 f32 = 1792B
constexpr int SM_Q      = 231168;   // queue broadcast slot
constexpr int FUSED_SMEM = 231296;

struct AccT { float a[2][3][2][4]; };   // [mt][gate][sub][q]

__device__ __forceinline__ void mma_section32(AccT& A, u32 ab, u32 wb,
                                              int wm, int wn,
                                              int a_row, int a_colh,
                                              int b_row, int b_colh)
{
    #pragma unroll
    for (int ks = 0; ks < 4; ks++) {
        u32 ahi[2][4], alo[2][4];
        #pragma unroll
        for (int mt = 0; mt < 2; mt++) {
            int r = wm * 32 + mt * 16 + a_row;
            u32 off = (u32)(r * 128) + (u32)((ks * 32 + a_colh) ^ ((r & 7) << 4));
            ldsm_x4(ahi[mt][0], ahi[mt][1], ahi[mt][2], ahi[mt][3], ab + off);
            ldsm_x4(alo[mt][0], alo[mt][1], alo[mt][2], alo[mt][3], ab + 8192 + off);
        }
        #pragma unroll
        for (int g = 0; g < 3; g++) {
            int rr = g * 64 + wn * 16 + b_row;
            u32 off = (u32)(rr * 128) + (u32)((ks * 32 + b_colh) ^ ((rr & 7) << 4));
            u32 bh[4], bl[4];
            ldsm_x4(bh[0], bh[1], bh[2], bh[3], wb + off);
            ldsm_x4(bl[0], bl[1], bl[2], bl[3], wb + SM_WLO_O + off);
            #pragma unroll
            for (int mt = 0; mt < 2; mt++) {
                mma_bf16(A.a[mt][g][0], ahi[mt], bh);        // hi*whi
                mma_bf16(A.a[mt][g][1], ahi[mt], bh + 2);
                mma_bf16(A.a[mt][g][0], ahi[mt], bl);        // hi*wlo
                mma_bf16(A.a[mt][g][1], ahi[mt], bl + 2);
                mma_bf16(A.a[mt][g][0], alo[mt], bh);        // lo*whi
                mma_bf16(A.a[mt][g][1], alo[mt], bh + 2);
            }
        }
    }
}

__global__ void __launch_bounds__(512, 1)
fused_persist(const float* __restrict__ h0,
              const float* __restrict__ x,
              const float* __restrict__ w_ih,
              const float* __restrict__ w_hh,
              const float* __restrict__ b_ih,
              const float* __restrict__ b_hh,
              const float* __restrict__ w1, const float* __restrict__ b1,
              const float* __restrict__ w2, const float* __restrict__ b2,
              const float* __restrict__ w3, const float* __restrict__ b3,
              float* __restrict__ out)
{
    extern __shared__ char smem[];
    const u32 sb = smem_u32(smem);
    const int tid  = threadIdx.x;

    // =====================================================================
    // GRU producer part
    // =====================================================================
    if (blockIdx.x < NGRU) {
        float* sparam = (float*)(smem + SM_PRM);
        const int wid  = tid >> 5;
        const int lane = tid & 31;
        const int jc = blockIdx.x & 3;
        const int bg = blockIdx.x >> 2;
        const int j0 = jc * 64;
        const int b0 = bg * 64;
        const bool mmaw = wid < 8;
        const int wm = (wid >> 2) & 1;
        const int wn = wid & 3;
        const int stid = tid - 256;

        if (tid < 64) {
            int jg = j0 + tid;
            sparam[tid]        = w_ih[jg];
            sparam[64 + tid]   = w_ih[H + jg];
            sparam[128 + tid]  = w_ih[2 * H + jg];
            sparam[192 + tid]  = b_ih[jg]         + b_hh[jg];
            sparam[256 + tid]  = b_ih[H + jg]     + b_hh[H + jg];
            sparam[320 + tid]  = b_ih[2 * H + jg];
            sparam[384 + tid]  = b_hh[2 * H + jg];
        }

        // inline weight split: fp32 w_hh slice -> bf16 hi/lo, SW128, resident
        for (int c = 0; c < 4; c++) {
            for (int f = tid; f < 192 * 16; f += 512) {
                int rr = f >> 4, cc = f & 15;          // cc: 4 floats each
                int g = rr >> 6, jj = rr & 63;
                float4 w = *(const float4*)&w_hh[((size_t)(g * H + j0 + jj)) * H
                                                 + c * 64 + cc * 4];
                __nv_bfloat162 h0p = __floats2bfloat162_rn(w.x, w.y);
                __nv_bfloat162 h1p = __floats2bfloat162_rn(w.z, w.w);
                __nv_bfloat162 l0p = __floats2bfloat162_rn(w.x - __bfloat162float(h0p.x),
                                                           w.y - __bfloat162float(h0p.y));
                __nv_bfloat162 l1p = __floats2bfloat162_rn(w.z - __bfloat162float(h1p.x),
                                                           w.w - __bfloat162float(h1p.y));
                u32 o = (u32)(c * 24576 + rr * 128) + (u32)((cc * 8) ^ ((rr & 7) << 4));
                *(u32*)(smem + SM_W + o)               = bf2u(h0p);
                *(u32*)(smem + SM_W + o + 4)           = bf2u(h1p);
                *(u32*)(smem + SM_W + SM_WLO_O + o)     = bf2u(l0p);
                *(u32*)(smem + SM_W + SM_WLO_O + o + 4) = bf2u(l1p);
            }
        }

        const int a_row  = lane & 15;
        const int a_colh = (lane >> 4) * 16;
        const int b_row  = ((lane >> 4) << 3) + (lane & 7);
        const int b_colh = ((lane >> 3) & 1) * 16;
        const int l4 = lane >> 2;
        const int lp = lane & 3;

        float2 hst[4][2];
        if (mmaw) {
            #pragma unroll
            for (int e = 0; e < 4; e++)
                #pragma unroll
                for (int sub = 0; sub < 2; sub++) {
                    int rowg = b0 + wm * 32 + (e >> 1) * 16 + (e & 1) * 8 + l4;
                    int jl = wn * 16 + 8 * sub + 2 * lp;
                    hst[e][sub] = *(const float2*)&h0[(size_t)rowg * H + j0 + jl];
                }
        }

        // pre-stage OWN chunk (jc) of h0 into buf0
        #pragma unroll
        for (int i = 0; i < 4; i++) {
            int f = tid + i * 512;
            int row = f >> 5, kp = f & 31;
            float2 hv = *(const float2*)&h0[(size_t)(b0 + row) * H + jc * 64 + 2 * kp];
            __nv_bfloat162 h2 = __floats2bfloat162_rn(hv.x, hv.y);
            __nv_bfloat162 l2 = __floats2bfloat162_rn(hv.x - __bfloat162float(h2.x),
                                                      hv.y - __bfloat162float(h2.y));
            u32 off = (u32)(row * 128) + (u32)((kp * 4) ^ ((row & 7) << 4));
            *(u32*)(smem + SM_A + off)        = bf2u(h2);
            *(u32*)(smem + SM_A + 8192 + off) = bf2u(l2);
        }
        __syncthreads();

        const u32 ab0 = sb + SM_A;
        const u32 ab1 = sb + SM_A + 16384;
        const int c1 = (jc + 1) & 3, c2 = (jc + 2) & 3, c3 = (jc + 3) & 3;

        #define STAGE_CP(c, dst)                                                 \
            do {                                                                 \
                size_t base_ = ((size_t)(t - 1) * B + b0) * 128 + (size_t)(c) * 32; \
                _Pragma("unroll")                                                \
                for (int i_ = 0; i_ < 2; i_++) {                                 \
                    int f_ = stid + i_ * 256;                                    \
                    int rr_ = f_ >> 3, cc_ = f_ & 7;                             \
                    u32 o_ = (u32)(rr_ * 128) + (u32)((cc_ * 16) ^ ((rr_ & 7) << 4)); \
                    cp16((dst) + o_,        &g_hhi[base_ + (size_t)rr_ * 128 + cc_ * 4]); \
                    cp16((dst) + 8192 + o_, &g_hlo[base_ + (size_t)rr_ * 128 + cc_ * 4]); \
                }                                                                \
                cp_commit();                                                     \
                cp_wait_group<0>();                                              \
            } while (0)

        #define STAGE_CVT(c, dstc)                                               \
            do {                                                                 \
                _Pragma("unroll")                                                \
                for (int i_ = 0; i_ < 8; i_++) {                                 \
                    int f_ = stid + i_ * 256;                                    \
                    int row_ = f_ >> 5, kp_ = f_ & 31;                           \
                    float2 hv_ = *(const float2*)&h0[(size_t)(b0 + row_) * H + (c) * 64 + 2 * kp_]; \
                    __nv_bfloat162 h2_ = __floats2bfloat162_rn(hv_.x, hv_.y);    \
                    __nv_bfloat162 l2_ = __floats2bfloat162_rn(                  \
                        hv_.x - __bfloat162float(h2_.x),                         \
                        hv_.y - __bfloat162float(h2_.y));                        \
                    u32 o_ = (u32)(row_ * 128) + (u32)((kp_ * 4) ^ ((row_ & 7) << 4)); \
                    *(u32*)((dstc) + o_)        = bf2u(h2_);                     \
                    *(u32*)((dstc) + 8192 + o_) = bf2u(l2_);                     \
                }                                                                \
            } while (0)

        for (int t = 0; t < T; t++) {
            AccT A;
            float xvv[4];

            // phase 0: MMA own chunk; staging polls + stages c1
            if (mmaw) {
                #pragma unroll
                for (int mt = 0; mt < 2; mt++)
                    #pragma unroll
                    for (int g = 0; g < 3; g++)
                        #pragma unroll
                        for (int s = 0; s < 2; s++)
                            #pragma unroll
                            for (int q = 0; q < 4; q++) A.a[mt][g][s][q] = 0.f;
                #pragma unroll
                for (int e = 0; e < 4; e++)
                    xvv[e] = x[(size_t)t * B + b0 + wm * 32 + (e >> 1) * 16
                               + (e & 1) * 8 + l4];
                mma_section32(A, ab0, sb + SM_W + jc * 24576,
                              wm, wn, a_row, a_colh, b_row, b_colh);
            } else {
                if (t > 0) {
                    if (lane == 0) {
                        u32 g;
                        do {
                            asm volatile("ld.acquire.gpu.global.u32 %0, [%1];"
                                         : "=r"(g) : "l"(&g_cnt[bg * 32]));
                        } while ((int)(g - (u32)(4 * t)) < 0);
                    }
                    __syncwarp();
                    STAGE_CP(c1, ab1);
                } else {
                    STAGE_CVT(c1, smem + SM_A + 16384);
                }
            }
            __syncthreads();

            // phase 1: MMA c1 (buf1); staging stages c2 -> buf0
            if (mmaw) {
                mma_section32(A, ab1, sb + SM_W + c1 * 24576,
                              wm, wn, a_row, a_colh, b_row, b_colh);
            } else {
                if (t > 0) STAGE_CP(c2, ab0);
                else       STAGE_CVT(c2, smem + SM_A);
            }
            __syncthreads();

            // phase 2: MMA c2 (buf0); staging stages c3 -> buf1
            if (mmaw) {
                mma_section32(A, ab0, sb + SM_W + c2 * 24576,
                              wm, wn, a_row, a_colh, b_row, b_colh);
            } else {
                if (t > 0) STAGE_CP(c3, ab1);
                else       STAGE_CVT(c3, smem + SM_A + 16384);
            }
            __syncthreads();

            // phase 3: MMA c3 (buf1); epilogue
            if (mmaw) {
                mma_section32(A, ab1, sb + SM_W + c3 * 24576,
                              wm, wn, a_row, a_colh, b_row, b_colh);

                #pragma unroll
                for (int mt = 0; mt < 2; mt++)
                    #pragma unroll
                    for (int half = 0; half < 2; half++) {
                        int e = mt * 2 + half;
                        int rowl = wm * 32 + mt * 16 + half * 8 + l4;
                        int rowg = b0 + rowl;
                        float xv = xvv[e];
                        #pragma unroll
                        for (int sub = 0; sub < 2; sub++) {
                            int jl = wn * 16 + 8 * sub + 2 * lp;
                            float hn0, hn1;
                            {
                                int j = jl;
                                float r = fast_sigmoid(xv * sparam[j] + sparam[192 + j]
                                                       + A.a[mt][0][sub][half * 2]);
                                float z = fast_sigmoid(xv * sparam[64 + j] + sparam[256 + j]
                                                       + A.a[mt][1][sub][half * 2]);
                                float n = fast_tanh(xv * sparam[128 + j] + sparam[320 + j]
                                                    + r * (A.a[mt][2][sub][half * 2]
                                                           + sparam[384 + j]));
                                hn0 = (1.f - z) * n + z * hst[e][sub].x;
                            }
                            {
                                int j = jl + 1;
                                float r = fast_sigmoid(xv * sparam[j] + sparam[192 + j]
                                                       + A.a[mt][0][sub][half * 2 + 1]);
                                float z = fast_sigmoid(xv * sparam[64 + j] + sparam[256 + j]
                                                       + A.a[mt][1][sub][half * 2 + 1]);
                                float n = fast_tanh(xv * sparam[128 + j] + sparam[320 + j]
                                                    + r * (A.a[mt][2][sub][half * 2 + 1]
                                                           + sparam[384 + j]));
                                hn1 = (1.f - z) * n + z * hst[e][sub].y;
                            }
                            hst[e][sub] = make_float2(hn0, hn1);

                            __nv_bfloat162 h2 = __floats2bfloat162_rn(hn0, hn1);
                            __nv_bfloat162 l2 = __floats2bfloat162_rn(
                                hn0 - __bfloat162float(h2.x),
                                hn1 - __bfloat162float(h2.y));
                            int kp = wn * 8 + 4 * sub + lp;
                            size_t gi = ((size_t)t * B + rowg) * 128 + jc * 32 + kp;
                            u32 uhi = bf2u(h2), ulo = bf2u(l2);
                            g_hhi[gi] = uhi;
                            g_hlo[gi] = ulo;
                            u32 off = (u32)(rowl * 128)
                                      + (u32)((kp * 4) ^ ((rowl & 7) << 4));
                            *(u32*)(smem + SM_A + off)        = uhi;
                            *(u32*)(smem + SM_A + 8192 + off) = ulo;
                        }
                    }
            }

            // release h_t
            __threadfence();
            __syncthreads();
            if (tid == 0) atomicAdd(&g_cnt[bg * 32], 1u);
        }
        #undef STAGE_CP
        #undef STAGE_CVT
        __syncthreads();
    }

    // =====================================================================
    // Consumer part (all blocks): MLP tiles + h_last copy tiles
    // =====================================================================
    {
        float* sm  = (float*)smem;
        float* xt  = sm;            // [64][256]
        float* w1s = sm + 16384;    // [64][260]
        float* h1s = sm + 33024;    // [64][64]
        float* h2t = sm + 37120;    // [64][66]
        float* w3s = sm;            // alias xt
        float* w2s = sm + 16384;    // alias w1s
        u32* qs = (u32*)(smem + SM_Q);

        const int jp = tid & 31;
        const int rg = (tid >> 5) & 7;
        const bool act = tid < 256;

        for (;;) {
            __syncthreads();
            if (tid == 0) *qs = atomicAdd(&g_q, 1u);
            __syncthreads();
            u32 q = *qs;
            if (q >= (u32)NTILE_TOT) {
                // last exit-pop globally -> reset sync state for next replay
                if (q == (u32)(NTILE_TOT + GRID_P - 1) && tid == 0) {
                    for (int i = 0; i < 32; i++) g_cnt[i * 32] = 0;
                    __threadfence();
                    atomicExch(&g_q, 0u);
                }
                break;
            }

            if (q >= (u32)NTILE) {
                // ---- h_last copy tile: 256 rows, gated on 4 bgs complete ----
                int seg = (int)(q - NTILE);
                if (tid < 4) {
                    u32 g;
                    do {
                        asm volatile("ld.acquire.gpu.global.u32 %0, [%1];"
                                     : "=r"(g) : "l"(&g_cnt[(seg * 4 + tid) * 32]));
                    } while ((int)(g - (u32)(4 * T)) < 0);
                }
                __syncthreads();
                size_t base = ((size_t)(T - 1) * B + (size_t)seg * 256) * 128;
                float* dst = out + (size_t)T * B * OUTD + (size_t)seg * 256 * H;
                for (int i = tid; i < 256 * 128; i += 512) {
                    float2 a = u2f2(g_hhi[base + i]);
                    float2 b = u2f2(g_hlo[base + i]);
                    *(float2*)&dst[2 * i] = make_float2(a.x + b.x, a.y + b.y);
                }
                continue;
            }

            int tt  = (int)(q >> 5);
            int bgq = (int)(q & 31);

            if (tid == 0) {
                u32 target = (u32)(4 * (tt + 1)), g;
                do {
                    asm volatile("ld.acquire.gpu.global.u32 %0, [%1];"
                                 : "=r"(g) : "l"(&g_cnt[bgq * 32]));
                } while ((int)(g - target) < 0);
            }
            __syncthreads();

            const size_t row0 = (size_t)q * RROWS;

            // reconstruct xt fp32 from bf16 hi/lo
            {
                const u32* hh = g_hhi + row0 * 128;
                const u32* ll = g_hlo + row0 * 128;
                for (int i = tid; i < RROWS * 128; i += 512) {
                    float2 a = u2f2(hh[i]);
                    float2 b = u2f2(ll[i]);
                    int row = i >> 7, kp = i & 127;
                    *(float2*)&xt[row * 256 + 2 * kp] = make_float2(a.x + b.x, a.y + b.y);
                }
            }
            for (int f = tid; f < H * H1; f += 512) {
                int jj = f & 63; int k = f >> 6;
                w1s[jj * 260 + k] = w1[f];
            }
            __syncthreads();

            // Stage 1
            if (act) {
                float acc[8][2];
                #pragma unroll
                for (int i = 0; i < 8; i++) { acc[i][0] = 0.f; acc[i][1] = 0.f; }
                #pragma unroll 4
                for (int k = 0; k < H; k += 4) {
                    float4 wa = *(const float4*)&w1s[(2 * jp) * 260 + k];
                    float4 wb = *(const float4*)&w1s[(2 * jp + 1) * 260 + k];
                    #pragma unroll
                    for (int i = 0; i < 8; i++) {
                        float4 xv = *(const float4*)&xt[(rg * 8 + i) * H + k];
                        acc[i][0] += xv.x * wa.x + xv.y * wa.y + xv.z * wa.z + xv.w * wa.w;
                        acc[i][1] += xv.x * wb.x + xv.y * wb.y + xv.z * wb.z + xv.w * wb.w;
                    }
                }
                float ba = b1[2 * jp], bb = b1[2 * jp + 1];
                #pragma unroll
                for (int i = 0; i < 8; i++) {
                    h1s[(rg * 8 + i) * 64 + 2 * jp]     = fast_elu(acc[i][0] + ba);
                    h1s[(rg * 8 + i) * 64 + 2 * jp + 1] = fast_elu(acc[i][1] + bb);
                }
            }
            __syncthreads();

            for (int f = tid; f < H1 * H2; f += 512) {
                int jj = f & 63; int k = f >> 6;
                w2s[jj * 68 + k] = w2[f];
            }
            __syncthreads();

            // Stage 2 (h2 transposed)
            if (act) {
                float acc[8][2];
                #pragma unroll
                for (int i = 0; i < 8; i++) { acc[i][0] = 0.f; acc[i][1] = 0.f; }
                #pragma unroll
                for (int k = 0; k < H1; k += 4) {
                    float4 wa = *(const float4*)&w2s[(2 * jp) * 68 + k];
                    float4 wb = *(const float4*)&w2s[(2 * jp + 1) * 68 + k];
                    #pragma unroll
                    for (int i = 0; i < 8; i++) {
                        float4 xv = *(const float4*)&h1s[(rg * 8 + i) * 64 + k];
                        acc[i][0] += xv.x * wa.x + xv.y * wa.y + xv.z * wa.z + xv.w * wa.w;
                        acc[i][1] += xv.x * wb.x + xv.y * wb.y + xv.z * wb.z + xv.w * wb.w;
                    }
                }
                float ba = b2[2 * jp], bb = b2[2 * jp + 1];
                #pragma unroll
                for (int i = 0; i < 8; i++) {
                    int row = rg * 8 + i;
                    h2t[(2 * jp) * 66 + row]     = fast_elu(acc[i][0] + ba);
                    h2t[(2 * jp + 1) * 66 + row] = fast_elu(acc[i][1] + bb);
                }
            }
            __syncthreads();

            // Stage 3: packed fp32x2 over row pairs
            for (int c0 = 0; c0 < OUTD; c0 += 128) {
                for (int f = tid; f < 64 * 128; f += 512) {
                    int c = f & 127; int k = f >> 7;
                    int cg = c0 + c;
                    w3s[k * 128 + c] = (cg < OUTD) ? w3[(size_t)k * OUTD + cg] : 0.f;
                }
                __syncthreads();

                if (act) {
                    u64 acc[4][4];
                    #pragma unroll
                    for (int rp = 0; rp < 4; rp++)
                        #pragma unroll
                        for (int qq = 0; qq < 4; qq++) acc[rp][qq] = 0ull;

                    #pragma unroll 4
                    for (int k = 0; k < H2; k++) {
                        u64 wd[4];
                        #pragma unroll
                        for (int qq = 0; qq < 4; qq++) {
                            float w = w3s[k * 128 + jp + 32 * qq];
                            wd[qq] = pack2(w, w);
                        }
                        const float* hp = &h2t[k * 66 + rg * 8];
                        u64 hv0 = *(const u64*)(hp + 0);
                        u64 hv1 = *(const u64*)(hp + 2);
                        u64 hv2 = *(const u64*)(hp + 4);
                        u64 hv3 = *(const u64*)(hp + 6);
                        #pragma unroll
                        for (int qq = 0; qq < 4; qq++) {
                            acc[0][qq] = ffma2(hv0, wd[qq], acc[0][qq]);
                            acc[1][qq] = ffma2(hv1, wd[qq], acc[1][qq]);
                            acc[2][qq] = ffma2(hv2, wd[qq], acc[2][qq]);
                            acc[3][qq] = ffma2(hv3, wd[qq], acc[3][qq]);
                        }
                    }

                    #pragma unroll
                    for (int qq = 0; qq < 4; qq++) {
                        int cg = c0 + jp + 32 * qq;
                        if (cg < OUTD) {
                            float bq = b3[cg];
                            #pragma unroll
                            for (int rp = 0; rp < 4; rp++) {
                                float2 v = unpack2(acc[rp][qq]);
                                size_t row = row0 + rg * 8 + 2 * rp;
                                out[row * OUTD + cg]       = v.x + bq;
                                out[(row + 1) * OUTD + cg] = v.y + bq;
                            }
                        }
                    }
                }
                __syncthreads();
            }
        }
    }
}

// ---------------------------------------------------------------------------
extern "C" void kernel_launch(void* const* d_in, const int* in_sizes, int n_in,
                              void* d_out, int out_size)
{
    const float* x    = (const float*)d_in[0];
    const float* h0   = (const float*)d_in[1];
    const float* w_ih = (const float*)d_in[2];
    const float* w_hh = (const float*)d_in[3];
    const float* b_ih = (const float*)d_in[4];
    const float* b_hh = (const float*)d_in[5];
    const float* w1   = (const float*)d_in[6];
    const float* b1   = (const float*)d_in[7];
    const float* w2   = (const float*)d_in[8];
    const float* b2   = (const float*)d_in[9];
    const float* w3   = (const float*)d_in[10];
    const float* b3   = (const float*)d_in[11];
    float* out = (float*)d_out;

    cudaFuncSetAttribute(fused_persist,
                         cudaFuncAttributeMaxDynamicSharedMemorySize, FUSED_SMEM);

    fused_persist<<<GRID_P, 512, FUSED_SMEM>>>(h0, x, w_ih, w_hh, b_ih, b_hh,
                                               w1, b1, w2, b2, w3, b3, out);
}